// round 16
// baseline (speedup 1.0000x reference)
#include <cuda_runtime.h>
#include <cuda_fp16.h>
#include <cstdint>

// ---------------- scratch (__device__ globals; no allocation allowed) -------
__device__ __half g_xs[4096 * 1024];            // x as fp16
__device__ __half g_ks[4096 * 1024];            // K projection fp16
__device__ __half g_att[4096 * 1024];           // attention out fp16
__device__ __half g_wk[1024 * 1024];            // W_attn K-slice, [n][k] fp16
__device__ __half g_wp[1024 * 1024];            // W_proj, [n][k] fp16

// ---------------- PTX helpers (all compute_103-safe) ------------------------
__device__ __forceinline__ float fast_exp2(float x) {
    float y; asm("ex2.approx.ftz.f32 %0, %1;" : "=f"(y) : "f"(x)); return y;
}
__device__ __forceinline__ uint32_t smem_u32(const void* p) {
    uint32_t a;
    asm("{ .reg .u64 t; cvta.to.shared.u64 t, %1; cvt.u32.u64 %0, t; }" : "=r"(a) : "l"(p));
    return a;
}
__device__ __forceinline__ void cp_async16(uint32_t dst, const void* src) {
    asm volatile("cp.async.cg.shared.global [%0], [%1], 16;" :: "r"(dst), "l"(src));
}
__device__ __forceinline__ void cp_commit() {
    asm volatile("cp.async.commit_group;" ::: "memory");
}
__device__ __forceinline__ void cp_wait1() {
    asm volatile("cp.async.wait_group 1;" ::: "memory");
}
__device__ __forceinline__ void cp_wait2() {
    asm volatile("cp.async.wait_group 2;" ::: "memory");
}
__device__ __forceinline__ void cp_wait0() {
    asm volatile("cp.async.wait_group 0;" ::: "memory");
}
__device__ __forceinline__ void ldsm4(uint32_t& r0, uint32_t& r1, uint32_t& r2,
                                      uint32_t& r3, uint32_t addr) {
    asm volatile("ldmatrix.sync.aligned.m8n8.x4.shared.b16 {%0,%1,%2,%3}, [%4];"
                 : "=r"(r0), "=r"(r1), "=r"(r2), "=r"(r3) : "r"(addr));
}
__device__ __forceinline__ void ldsm4t(uint32_t& r0, uint32_t& r1, uint32_t& r2,
                                       uint32_t& r3, uint32_t addr) {
    asm volatile("ldmatrix.sync.aligned.m8n8.x4.trans.shared.b16 {%0,%1,%2,%3}, [%4];"
                 : "=r"(r0), "=r"(r1), "=r"(r2), "=r"(r3) : "r"(addr));
}
__device__ __forceinline__ void mma_f16(float* c, const uint32_t* a,
                                        uint32_t b0, uint32_t b1) {
    asm volatile(
        "mma.sync.aligned.m16n8k16.row.col.f32.f16.f16.f32 "
        "{%0,%1,%2,%3}, {%4,%5,%6,%7}, {%8,%9}, {%0,%1,%2,%3};"
        : "+f"(c[0]), "+f"(c[1]), "+f"(c[2]), "+f"(c[3])
        : "r"(a[0]), "r"(a[1]), "r"(a[2]), "r"(a[3]), "r"(b0), "r"(b1));
}
__device__ __forceinline__ uint32_t pack_h2(float a, float b) {
    __half2 h = __float22half2_rn(make_float2(a, b));
    return *(uint32_t*)&h;
}

// ---------------- merged prep: x->fp16; W transposes (single fp16) ----------
__global__ __launch_bounds__(256) void prep_kernel(
    const float* __restrict__ X, __half* __restrict__ XO,
    const float* __restrict__ Wk, const float* __restrict__ Wp,
    __half* __restrict__ WkO, __half* __restrict__ WpO)
{
    __shared__ float t[32][33];
    int bid = blockIdx.x;
    if (bid < 4096) {
        int i = bid * 256 + threadIdx.x;
        float4 v = ((const float4*)X)[i];
        ((__half2*)XO)[i * 2]     = __float22half2_rn(make_float2(v.x, v.y));
        ((__half2*)XO)[i * 2 + 1] = __float22half2_rn(make_float2(v.z, v.w));
        return;
    }
    bid -= 4096;
    const float* W; __half* O; int ldw;
    if (bid < 1024) { W = Wk; ldw = 3072; O = WkO; }
    else { bid -= 1024; W = Wp; ldw = 1024; O = WpO; }
    int n0 = (bid & 31) * 32, k0 = (bid >> 5) * 32;
    int tx = threadIdx.x & 31, ty = threadIdx.x >> 5;
#pragma unroll
    for (int p = 0; p < 4; p++)
        t[ty + 8 * p][tx] = W[(size_t)(k0 + ty + 8 * p) * ldw + n0 + tx];
    __syncthreads();
#pragma unroll
    for (int p = 0; p < 4; p++)
        O[(size_t)(n0 + ty + 8 * p) * 1024 + k0 + tx] =
            __float2half_rn(t[tx][ty + 8 * p]);
}

// ---------------- tensor-core GEMM: C = A @ B^T + bias (single fp16) --------
// Tile M=128, N=128, BK=32, 256 threads (8 warps = 2m x 4n, warp 64x32),
// 4-stage cp.async pipeline, 2 CTAs/SM (256 CTAs, one wave, sync overlap).
#define G3_ROWB 80
#define G3_STAGE 20480
#define G3_SMEM (4 * G3_STAGE)   // 81920

__global__ __launch_bounds__(256, 2) void gemm_mma(
    const __half* __restrict__ A, const __half* __restrict__ B,
    const float* __restrict__ bias, float* __restrict__ C,
    __half* __restrict__ Ch)
{
    extern __shared__ char smem[];
    const uint32_t sb = smem_u32(smem);
    const int tid = threadIdx.x;
    const int wid = tid >> 5;       // 0..7
    const int lane = tid & 31;
    const int wm = wid >> 2;        // 0..1, 64 rows each
    const int wn = wid & 3;         // 0..3, 32 cols each
    const int m0 = blockIdx.y * 128, n0 = blockIdx.x * 128;

    const uint32_t a_off = (uint32_t)((wm * 64 + (lane & 15)) * G3_ROWB + (lane >> 4) * 16);
    const uint32_t b_off = (uint32_t)(128 * G3_ROWB
                                      + (wn * 32 + (lane & 15)) * G3_ROWB + (lane >> 4) * 16);

    // ---- hoisted loader addressing: 4 fixed (src, dst) pairs per thread ----
    const char* lsrc[4];
    uint32_t ldst[4];
#pragma unroll
    for (int p = 0; p < 4; p++) {
        int u = tid + p * 256;          // 0..1023; 256 rows x 4 c16
        int row = u >> 2, c16 = u & 3;
        lsrc[p] = (row < 128)
            ? (const char*)A + (size_t)(m0 + row) * 2048 + c16 * 16
            : (const char*)B + (size_t)(n0 + row - 128) * 2048 + c16 * 16;
        ldst[p] = sb + (uint32_t)(row * G3_ROWB + c16 * 16);
    }

    float acc[4][4][4];
#pragma unroll
    for (int i = 0; i < 4; i++)
#pragma unroll
        for (int j = 0; j < 4; j++)
#pragma unroll
            for (int r = 0; r < 4; r++) acc[i][j][r] = 0.0f;

    // prologue: chunks 0,1,2
#pragma unroll
    for (int c = 0; c < 3; c++) {
        const uint32_t stg = (uint32_t)c * G3_STAGE;
#pragma unroll
        for (int p = 0; p < 4; p++)
            cp_async16(ldst[p] + stg, lsrc[p] + c * 64);
        cp_commit();
    }

    for (int c = 0; c < 32; c++) {
        cp_wait2();
        __syncthreads();
        if (c + 3 < 32) {
            const uint32_t stg = (uint32_t)((c + 3) & 3) * G3_STAGE;
#pragma unroll
            for (int p = 0; p < 4; p++)
                cp_async16(ldst[p] + stg, lsrc[p] + (c + 3) * 64);
        }
        cp_commit();

        const uint32_t st = (uint32_t)(c & 3) * G3_STAGE;
#pragma unroll
        for (int kk = 0; kk < 2; kk++) {
            uint32_t bh[2][4];
#pragma unroll
            for (int p = 0; p < 2; p++) {
                uint32_t addr = sb + st + b_off + (uint32_t)(p * 16 * G3_ROWB) + kk * 32;
                ldsm4(bh[p][0], bh[p][1], bh[p][2], bh[p][3], addr);
            }
            uint32_t ah[4][4];
#pragma unroll
            for (int mf = 0; mf < 4; mf++) {
                uint32_t addr = sb + st + a_off + (uint32_t)(mf * 16 * G3_ROWB) + kk * 32;
                ldsm4(ah[mf][0], ah[mf][1], ah[mf][2], ah[mf][3], addr);
            }
#pragma unroll
            for (int mf = 0; mf < 4; mf++)
#pragma unroll
                for (int nf = 0; nf < 4; nf++) {
                    const int p = nf >> 1, hh = nf & 1;
                    mma_f16(acc[mf][nf], ah[mf], bh[p][hh], bh[p][2 + hh]);
                }
        }
    }

    // epilogue
#pragma unroll
    for (int nf = 0; nf < 4; nf++) {
        int n = n0 + wn * 32 + nf * 8 + (lane & 3) * 2;
        float2 bv = *(const float2*)(bias + n);
#pragma unroll
        for (int mf = 0; mf < 4; mf++) {
            int m = m0 + wm * 64 + mf * 16 + (lane >> 2);
            float2 o0 = {acc[mf][nf][0] + bv.x, acc[mf][nf][1] + bv.y};
            float2 o1 = {acc[mf][nf][2] + bv.x, acc[mf][nf][3] + bv.y};
            if (Ch) {
                *(__half2*)(Ch + (size_t)m * 1024 + n) =
                    __float22half2_rn(make_float2(o0.x, o0.y));
                *(__half2*)(Ch + (size_t)(m + 8) * 1024 + n) =
                    __float22half2_rn(make_float2(o1.x, o1.y));
            } else {
                *(float2*)(C + (size_t)m * 1024 + n) = o0;
                *(float2*)(C + (size_t)(m + 8) * 1024 + n) = o1;
            }
        }
    }
}

// ---------------- FA2-style attention (single-fp16 K throughout) ------------
#define ROWB 144
#define AK0 18432
#define AKST 18432
#define ATTN_SMEM_B (18432 + 2 * 18432)

__global__ __launch_bounds__(256, 2) void attn_mma(
    const __half* __restrict__ K, __half* __restrict__ Out)
{
    extern __shared__ char smem[];
    const uint32_t sb = smem_u32(smem);
    const int tid = threadIdx.x;
    const int wid = tid >> 5;
    const int lane = tid & 31;
    const int g = lane >> 2;
    const int tq = lane & 3;
    const int b = blockIdx.y >> 4;
    const int h = blockIdx.y & 15;
    const int q0 = blockIdx.x * 128;

    const char* Kb = (const char*)K + (size_t)b * 2048 * 2048 + h * 128;
    const float SC = 0.125f * 1.4426950408889634f;

#pragma unroll
    for (int q = 0; q < 4; q++) {
        int u = tid + q * 256;
        int row = u >> 3, c = u & 7;
        cp_async16(sb + row * ROWB + c * 16,
                   Kb + (size_t)(q0 + row) * 2048 + c * 16);
    }
#pragma unroll
    for (int q = 0; q < 4; q++) {
        int u = tid + q * 256;
        int row = u >> 3, c = u & 7;
        cp_async16(sb + AK0 + row * ROWB + c * 16, Kb + (size_t)row * 2048 + c * 16);
    }
    cp_commit();

    float m0 = -1e30f, m1 = -1e30f, l0 = 0.0f, l1 = 0.0f;
    float o[8][4];
#pragma unroll
    for (int nf = 0; nf < 8; nf++)
#pragma unroll
        for (int r = 0; r < 4; r++) o[nf][r] = 0.0f;

    const uint32_t qa_off = (uint32_t)((wid * 16 + (lane & 15)) * ROWB + (lane >> 4) * 16);
    const uint32_t kb_row = (uint32_t)((lane & 15) * ROWB + (lane >> 4) * 16);

    for (int kt = 0; kt < 16; kt++) {
        const uint32_t st = sb + AK0 + (uint32_t)(kt & 1) * AKST;
        if (kt + 1 < 16) {
            const uint32_t st2 = sb + AK0 + (uint32_t)((kt + 1) & 1) * AKST;
            const size_t j0 = (size_t)(kt + 1) * 128;
#pragma unroll
            for (int q = 0; q < 4; q++) {
                int u = tid + q * 256;
                int row = u >> 3, c = u & 7;
                cp_async16(st2 + row * ROWB + c * 16, Kb + (j0 + row) * 2048 + c * 16);
            }
            cp_commit();
            cp_wait1();
        } else {
            cp_wait0();
        }
        __syncthreads();

        // ---- S = Q K^T ----
        float s[16][4];
#pragma unroll
        for (int nf = 0; nf < 16; nf++)
#pragma unroll
            for (int r = 0; r < 4; r++) s[nf][r] = 0.0f;

#pragma unroll
        for (int kk = 0; kk < 4; kk++) {
            uint32_t qh[4];
            ldsm4(qh[0], qh[1], qh[2], qh[3], sb + qa_off + kk * 32);
#pragma unroll
            for (int nb = 0; nb < 8; nb++) {
                uint32_t kh[4];
                uint32_t addr = st + kb_row + (uint32_t)(nb * 16 * ROWB) + kk * 32;
                ldsm4(kh[0], kh[1], kh[2], kh[3], addr);
#pragma unroll
                for (int hh = 0; hh < 2; hh++)
                    mma_f16(s[2 * nb + hh], qh, kh[hh], kh[2 + hh]);
            }
        }

        // ---- online softmax (scale folded) ----
        float mx0 = -1e30f, mx1 = -1e30f;
#pragma unroll
        for (int nf = 0; nf < 16; nf++) {
            mx0 = fmaxf(mx0, fmaxf(s[nf][0], s[nf][1]));
            mx1 = fmaxf(mx1, fmaxf(s[nf][2], s[nf][3]));
        }
        mx0 = fmaxf(mx0, __shfl_xor_sync(0xffffffffu, mx0, 1));
        mx0 = fmaxf(mx0, __shfl_xor_sync(0xffffffffu, mx0, 2));
        mx1 = fmaxf(mx1, __shfl_xor_sync(0xffffffffu, mx1, 1));
        mx1 = fmaxf(mx1, __shfl_xor_sync(0xffffffffu, mx1, 2));
        float mn0 = fmaxf(m0, mx0), mn1 = fmaxf(m1, mx1);
        float c0 = fast_exp2((m0 - mn0) * SC), c1 = fast_exp2((m1 - mn1) * SC);
        m0 = mn0; m1 = mn1;
        l0 *= c0; l1 *= c1;
#pragma unroll
        for (int nf = 0; nf < 8; nf++) {
            o[nf][0] *= c0; o[nf][1] *= c0;
            o[nf][2] *= c1; o[nf][3] *= c1;
        }
        const float b0s = -mn0 * SC, b1s = -mn1 * SC;
        float rs0 = 0.0f, rs1 = 0.0f;
#pragma unroll
        for (int nf = 0; nf < 16; nf++) {
            s[nf][0] = fast_exp2(fmaf(s[nf][0], SC, b0s));
            s[nf][1] = fast_exp2(fmaf(s[nf][1], SC, b0s));
            s[nf][2] = fast_exp2(fmaf(s[nf][2], SC, b1s));
            s[nf][3] = fast_exp2(fmaf(s[nf][3], SC, b1s));
            rs0 += s[nf][0] + s[nf][1];
            rs1 += s[nf][2] + s[nf][3];
        }
        rs0 += __shfl_xor_sync(0xffffffffu, rs0, 1);
        rs0 += __shfl_xor_sync(0xffffffffu, rs0, 2);
        rs1 += __shfl_xor_sync(0xffffffffu, rs1, 1);
        rs1 += __shfl_xor_sync(0xffffffffu, rs1, 2);
        l0 += rs0; l1 += rs1;

        // ---- O += P V (single term; V via ldsm.trans) ----
#pragma unroll
        for (int t = 0; t < 8; t++) {
            uint32_t ph[4];
            ph[0] = pack_h2(s[2 * t][0], s[2 * t][1]);
            ph[1] = pack_h2(s[2 * t][2], s[2 * t][3]);
            ph[2] = pack_h2(s[2 * t + 1][0], s[2 * t + 1][1]);
            ph[3] = pack_h2(s[2 * t + 1][2], s[2 * t + 1][3]);
#pragma unroll
            for (int nb = 0; nb < 4; nb++) {
                uint32_t vh[4];
                uint32_t addr = st + kb_row + (uint32_t)(t * 16 * ROWB) + nb * 32;
                ldsm4t(vh[0], vh[1], vh[2], vh[3], addr);
#pragma unroll
                for (int hh = 0; hh < 2; hh++)
                    mma_f16(o[2 * nb + hh], ph, vh[2 * hh], vh[2 * hh + 1]);
            }
        }
        __syncthreads();
    }

    // ---- epilogue ----
    float inv0 = 1.0f / l0, inv1 = 1.0f / l1;
    int mr0 = q0 + wid * 16 + g;
#pragma unroll
    for (int nf = 0; nf < 8; nf++) {
        int d = h * 64 + nf * 8 + tq * 2;
        size_t i0 = ((size_t)b * 2048 + mr0) * 1024 + d;
        size_t i1 = i0 + 8 * 1024;
        *(__half2*)(Out + i0) = __float22half2_rn(
            make_float2(o[nf][0] * inv0, o[nf][1] * inv0));
        *(__half2*)(Out + i1) = __float22half2_rn(
            make_float2(o[nf][2] * inv1, o[nf][3] * inv1));
    }
}

// ---------------------------------------------------------------------------
extern "C" void kernel_launch(void* const* d_in, const int* in_sizes, int n_in,
                              void* d_out, int out_size) {
    const float* x      = (const float*)d_in[0];  // (2, 2048, 1024)
    const float* W_attn = (const float*)d_in[1];  // (1024, 3072)
    const float* b_attn = (const float*)d_in[2];  // (3072,)
    const float* W_proj = (const float*)d_in[3];  // (1024, 1024)
    const float* b_proj = (const float*)d_in[4];  // (1024,)
    float* out = (float*)d_out;                   // (2, 2048, 1024)

    __half *xs, *ks, *att, *wk, *wp;
    cudaGetSymbolAddress((void**)&xs, g_xs);
    cudaGetSymbolAddress((void**)&ks, g_ks);
    cudaGetSymbolAddress((void**)&att, g_att);
    cudaGetSymbolAddress((void**)&wk, g_wk);
    cudaGetSymbolAddress((void**)&wp, g_wp);

    cudaFuncSetAttribute(gemm_mma,
                         cudaFuncAttributeMaxDynamicSharedMemorySize, G3_SMEM);
    cudaFuncSetAttribute(attn_mma,
                         cudaFuncAttributeMaxDynamicSharedMemorySize, ATTN_SMEM_B);

    // Prep (one launch)
    prep_kernel<<<6144, 256>>>(x, xs, W_attn + 1024, W_proj, wk, wp);

    // Stage 1: K = x @ W_attn[:, D:2D] + b  -> single fp16
    gemm_mma<<<dim3(8, 32), 256, G3_SMEM>>>(xs, wk, b_attn + 1024, nullptr, ks);

    // Stage 2: FA2 attention -> att fp16
    attn_mma<<<dim3(16, 32), 256, ATTN_SMEM_B>>>(ks, att);

    // Stage 3: out = att @ W_proj + b_proj (fp32 out)
    gemm_mma<<<dim3(8, 32), 256, G3_SMEM>>>(att, wp, b_proj, out, nullptr);
}

// round 17
// speedup vs baseline: 1.0310x; 1.0310x over previous
#include <cuda_runtime.h>
#include <cuda_fp16.h>
#include <cstdint>

// ---------------- scratch (__device__ globals; no allocation allowed) -------
__device__ __half g_xs[4096 * 1024];            // x as fp16
__device__ __half g_ks[4096 * 1024];            // K projection fp16
__device__ __half g_att[4096 * 1024];           // attention out fp16
__device__ __half g_wk[1024 * 1024];            // W_attn K-slice, [n][k] fp16
__device__ __half g_wp[1024 * 1024];            // W_proj, [n][k] fp16

// ---------------- PTX helpers (all compute_103-safe) ------------------------
__device__ __forceinline__ float fast_exp2(float x) {
    float y; asm("ex2.approx.ftz.f32 %0, %1;" : "=f"(y) : "f"(x)); return y;
}
__device__ __forceinline__ uint32_t smem_u32(const void* p) {
    uint32_t a;
    asm("{ .reg .u64 t; cvta.to.shared.u64 t, %1; cvt.u32.u64 %0, t; }" : "=r"(a) : "l"(p));
    return a;
}
__device__ __forceinline__ void cp_async16(uint32_t dst, const void* src) {
    asm volatile("cp.async.cg.shared.global [%0], [%1], 16;" :: "r"(dst), "l"(src));
}
__device__ __forceinline__ void cp_commit() {
    asm volatile("cp.async.commit_group;" ::: "memory");
}
__device__ __forceinline__ void cp_wait1() {
    asm volatile("cp.async.wait_group 1;" ::: "memory");
}
__device__ __forceinline__ void cp_wait0() {
    asm volatile("cp.async.wait_group 0;" ::: "memory");
}
__device__ __forceinline__ void ldsm4(uint32_t& r0, uint32_t& r1, uint32_t& r2,
                                      uint32_t& r3, uint32_t addr) {
    asm volatile("ldmatrix.sync.aligned.m8n8.x4.shared.b16 {%0,%1,%2,%3}, [%4];"
                 : "=r"(r0), "=r"(r1), "=r"(r2), "=r"(r3) : "r"(addr));
}
__device__ __forceinline__ void ldsm4t(uint32_t& r0, uint32_t& r1, uint32_t& r2,
                                       uint32_t& r3, uint32_t addr) {
    asm volatile("ldmatrix.sync.aligned.m8n8.x4.trans.shared.b16 {%0,%1,%2,%3}, [%4];"
                 : "=r"(r0), "=r"(r1), "=r"(r2), "=r"(r3) : "r"(addr));
}
__device__ __forceinline__ void mma_f16(float* c, const uint32_t* a,
                                        uint32_t b0, uint32_t b1) {
    asm volatile(
        "mma.sync.aligned.m16n8k16.row.col.f32.f16.f16.f32 "
        "{%0,%1,%2,%3}, {%4,%5,%6,%7}, {%8,%9}, {%0,%1,%2,%3};"
        : "+f"(c[0]), "+f"(c[1]), "+f"(c[2]), "+f"(c[3])
        : "r"(a[0]), "r"(a[1]), "r"(a[2]), "r"(a[3]), "r"(b0), "r"(b1));
}
__device__ __forceinline__ uint32_t pack_h2(float a, float b) {
    __half2 h = __float22half2_rn(make_float2(a, b));
    return *(uint32_t*)&h;
}

// ---------------- merged prep: x->fp16; W transposes (single fp16) ----------
__global__ __launch_bounds__(256) void prep_kernel(
    const float* __restrict__ X, __half* __restrict__ XO,
    const float* __restrict__ Wk, const float* __restrict__ Wp,
    __half* __restrict__ WkO, __half* __restrict__ WpO)
{
    __shared__ float t[32][33];
    int bid = blockIdx.x;
    if (bid < 4096) {
        int i = bid * 256 + threadIdx.x;
        float4 v = ((const float4*)X)[i];
        ((__half2*)XO)[i * 2]     = __float22half2_rn(make_float2(v.x, v.y));
        ((__half2*)XO)[i * 2 + 1] = __float22half2_rn(make_float2(v.z, v.w));
        return;
    }
    bid -= 4096;
    const float* W; __half* O; int ldw;
    if (bid < 1024) { W = Wk; ldw = 3072; O = WkO; }
    else { bid -= 1024; W = Wp; ldw = 1024; O = WpO; }
    int n0 = (bid & 31) * 32, k0 = (bid >> 5) * 32;
    int tx = threadIdx.x & 31, ty = threadIdx.x >> 5;
#pragma unroll
    for (int p = 0; p < 4; p++)
        t[ty + 8 * p][tx] = W[(size_t)(k0 + ty + 8 * p) * ldw + n0 + tx];
    __syncthreads();
#pragma unroll
    for (int p = 0; p < 4; p++)
        O[(size_t)(n0 + ty + 8 * p) * 1024 + k0 + tx] =
            __float2half_rn(t[tx][ty + 8 * p]);
}

// ---------------- tensor-core GEMM: C = A @ B^T + bias (single fp16) --------
// Tile M=256, N=128, BK=64, 512 threads (16 warps, warp 64x32), 3-stage
// cp.async pipeline, ONE CTA per SM (128 CTAs, one wave). 16 chunks ->
// half the barrier count of the BK=32 version.
#define G4_ROWB 144
#define G4_STAGE 55296           // 384 rows x 144 B
#define G4_SMEM (3 * G4_STAGE)   // 165888

__global__ __launch_bounds__(512, 1) void gemm_mma(
    const __half* __restrict__ A, const __half* __restrict__ B,
    const float* __restrict__ bias, float* __restrict__ C,
    __half* __restrict__ Ch)
{
    extern __shared__ char smem[];
    const uint32_t sb = smem_u32(smem);
    const int tid = threadIdx.x;
    const int wid = tid >> 5;       // 0..15
    const int lane = tid & 31;
    const int wm = wid >> 2;        // 0..3, 64 rows each
    const int wn = wid & 3;         // 0..3, 32 cols each
    const int m0 = blockIdx.y * 256, n0 = blockIdx.x * 128;

    const uint32_t a_off = (uint32_t)((wm * 64 + (lane & 15)) * G4_ROWB + (lane >> 4) * 16);
    const uint32_t b_off = (uint32_t)(256 * G4_ROWB
                                      + (wn * 32 + (lane & 15)) * G4_ROWB + (lane >> 4) * 16);

    // ---- hoisted loader addressing: 6 fixed (src, dst) pairs per thread ----
    // chunk = 384 rows x 8 c16 units (128 B of k per row)
    const char* lsrc[6];
    uint32_t ldst[6];
#pragma unroll
    for (int p = 0; p < 6; p++) {
        int u = tid + p * 512;          // 0..3071
        int row = u >> 3, c16 = u & 7;
        lsrc[p] = (row < 256)
            ? (const char*)A + (size_t)(m0 + row) * 2048 + c16 * 16
            : (const char*)B + (size_t)(n0 + row - 256) * 2048 + c16 * 16;
        ldst[p] = sb + (uint32_t)(row * G4_ROWB + c16 * 16);
    }

    float acc[4][4][4];
#pragma unroll
    for (int i = 0; i < 4; i++)
#pragma unroll
        for (int j = 0; j < 4; j++)
#pragma unroll
            for (int r = 0; r < 4; r++) acc[i][j][r] = 0.0f;

    // prologue: chunks 0,1
#pragma unroll
    for (int c = 0; c < 2; c++) {
        const uint32_t stg = (uint32_t)c * G4_STAGE;
#pragma unroll
        for (int p = 0; p < 6; p++)
            cp_async16(ldst[p] + stg, lsrc[p] + c * 128);
        cp_commit();
    }

    const uint32_t stage_of[16] = {0, G4_STAGE, 2 * G4_STAGE,
                                   0, G4_STAGE, 2 * G4_STAGE,
                                   0, G4_STAGE, 2 * G4_STAGE,
                                   0, G4_STAGE, 2 * G4_STAGE,
                                   0, G4_STAGE, 2 * G4_STAGE, 0};

    for (int c = 0; c < 16; c++) {
        cp_wait1();           // group for chunk c complete
        __syncthreads();
        if (c + 2 < 16) {
            const uint32_t stg = stage_of[c + 2];
#pragma unroll
            for (int p = 0; p < 6; p++)
                cp_async16(ldst[p] + stg, lsrc[p] + (c + 2) * 128);
        }
        cp_commit();

        const uint32_t st = stage_of[c];
#pragma unroll
        for (int kk = 0; kk < 4; kk++) {
            uint32_t bh[2][4];
#pragma unroll
            for (int p = 0; p < 2; p++) {
                uint32_t addr = sb + st + b_off + (uint32_t)(p * 16 * G4_ROWB) + kk * 32;
                ldsm4(bh[p][0], bh[p][1], bh[p][2], bh[p][3], addr);
            }
            uint32_t ah[4][4];
#pragma unroll
            for (int mf = 0; mf < 4; mf++) {
                uint32_t addr = sb + st + a_off + (uint32_t)(mf * 16 * G4_ROWB) + kk * 32;
                ldsm4(ah[mf][0], ah[mf][1], ah[mf][2], ah[mf][3], addr);
            }
#pragma unroll
            for (int mf = 0; mf < 4; mf++)
#pragma unroll
                for (int nf = 0; nf < 4; nf++) {
                    const int p = nf >> 1, hh = nf & 1;
                    mma_f16(acc[mf][nf], ah[mf], bh[p][hh], bh[p][2 + hh]);
                }
        }
    }

    // epilogue
#pragma unroll
    for (int nf = 0; nf < 4; nf++) {
        int n = n0 + wn * 32 + nf * 8 + (lane & 3) * 2;
        float2 bv = *(const float2*)(bias + n);
#pragma unroll
        for (int mf = 0; mf < 4; mf++) {
            int m = m0 + wm * 64 + mf * 16 + (lane >> 2);
            float2 o0 = {acc[mf][nf][0] + bv.x, acc[mf][nf][1] + bv.y};
            float2 o1 = {acc[mf][nf][2] + bv.x, acc[mf][nf][3] + bv.y};
            if (Ch) {
                *(__half2*)(Ch + (size_t)m * 1024 + n) =
                    __float22half2_rn(make_float2(o0.x, o0.y));
                *(__half2*)(Ch + (size_t)(m + 8) * 1024 + n) =
                    __float22half2_rn(make_float2(o1.x, o1.y));
            } else {
                *(float2*)(C + (size_t)m * 1024 + n) = o0;
                *(float2*)(C + (size_t)(m + 8) * 1024 + n) = o1;
            }
        }
    }
}

// ---------------- FA2-style attention (single-fp16 K throughout) ------------
#define ROWB 144
#define AK0 18432
#define AKST 18432
#define ATTN_SMEM_B (18432 + 2 * 18432)

__global__ __launch_bounds__(256, 2) void attn_mma(
    const __half* __restrict__ K, __half* __restrict__ Out)
{
    extern __shared__ char smem[];
    const uint32_t sb = smem_u32(smem);
    const int tid = threadIdx.x;
    const int wid = tid >> 5;
    const int lane = tid & 31;
    const int g = lane >> 2;
    const int tq = lane & 3;
    const int b = blockIdx.y >> 4;
    const int h = blockIdx.y & 15;
    const int q0 = blockIdx.x * 128;

    const char* Kb = (const char*)K + (size_t)b * 2048 * 2048 + h * 128;
    const float SC = 0.125f * 1.4426950408889634f;

#pragma unroll
    for (int q = 0; q < 4; q++) {
        int u = tid + q * 256;
        int row = u >> 3, c = u & 7;
        cp_async16(sb + row * ROWB + c * 16,
                   Kb + (size_t)(q0 + row) * 2048 + c * 16);
    }
#pragma unroll
    for (int q = 0; q < 4; q++) {
        int u = tid + q * 256;
        int row = u >> 3, c = u & 7;
        cp_async16(sb + AK0 + row * ROWB + c * 16, Kb + (size_t)row * 2048 + c * 16);
    }
    cp_commit();

    float m0 = -1e30f, m1 = -1e30f, l0 = 0.0f, l1 = 0.0f;
    float o[8][4];
#pragma unroll
    for (int nf = 0; nf < 8; nf++)
#pragma unroll
        for (int r = 0; r < 4; r++) o[nf][r] = 0.0f;

    const uint32_t qa_off = (uint32_t)((wid * 16 + (lane & 15)) * ROWB + (lane >> 4) * 16);
    const uint32_t kb_row = (uint32_t)((lane & 15) * ROWB + (lane >> 4) * 16);

    for (int kt = 0; kt < 16; kt++) {
        const uint32_t st = sb + AK0 + (uint32_t)(kt & 1) * AKST;
        if (kt + 1 < 16) {
            const uint32_t st2 = sb + AK0 + (uint32_t)((kt + 1) & 1) * AKST;
            const size_t j0 = (size_t)(kt + 1) * 128;
#pragma unroll
            for (int q = 0; q < 4; q++) {
                int u = tid + q * 256;
                int row = u >> 3, c = u & 7;
                cp_async16(st2 + row * ROWB + c * 16, Kb + (j0 + row) * 2048 + c * 16);
            }
            cp_commit();
            cp_wait1();
        } else {
            cp_wait0();
        }
        __syncthreads();

        // ---- S = Q K^T ----
        float s[16][4];
#pragma unroll
        for (int nf = 0; nf < 16; nf++)
#pragma unroll
            for (int r = 0; r < 4; r++) s[nf][r] = 0.0f;

#pragma unroll
        for (int kk = 0; kk < 4; kk++) {
            uint32_t qh[4];
            ldsm4(qh[0], qh[1], qh[2], qh[3], sb + qa_off + kk * 32);
#pragma unroll
            for (int nb = 0; nb < 8; nb++) {
                uint32_t kh[4];
                uint32_t addr = st + kb_row + (uint32_t)(nb * 16 * ROWB) + kk * 32;
                ldsm4(kh[0], kh[1], kh[2], kh[3], addr);
#pragma unroll
                for (int hh = 0; hh < 2; hh++)
                    mma_f16(s[2 * nb + hh], qh, kh[hh], kh[2 + hh]);
            }
        }

        // ---- online softmax (scale folded) ----
        float mx0 = -1e30f, mx1 = -1e30f;
#pragma unroll
        for (int nf = 0; nf < 16; nf++) {
            mx0 = fmaxf(mx0, fmaxf(s[nf][0], s[nf][1]));
            mx1 = fmaxf(mx1, fmaxf(s[nf][2], s[nf][3]));
        }
        mx0 = fmaxf(mx0, __shfl_xor_sync(0xffffffffu, mx0, 1));
        mx0 = fmaxf(mx0, __shfl_xor_sync(0xffffffffu, mx0, 2));
        mx1 = fmaxf(mx1, __shfl_xor_sync(0xffffffffu, mx1, 1));
        mx1 = fmaxf(mx1, __shfl_xor_sync(0xffffffffu, mx1, 2));
        float mn0 = fmaxf(m0, mx0), mn1 = fmaxf(m1, mx1);
        float c0 = fast_exp2((m0 - mn0) * SC), c1 = fast_exp2((m1 - mn1) * SC);
        m0 = mn0; m1 = mn1;
        l0 *= c0; l1 *= c1;
#pragma unroll
        for (int nf = 0; nf < 8; nf++) {
            o[nf][0] *= c0; o[nf][1] *= c0;
            o[nf][2] *= c1; o[nf][3] *= c1;
        }
        const float b0s = -mn0 * SC, b1s = -mn1 * SC;
        float rs0 = 0.0f, rs1 = 0.0f;
#pragma unroll
        for (int nf = 0; nf < 16; nf++) {
            s[nf][0] = fast_exp2(fmaf(s[nf][0], SC, b0s));
            s[nf][1] = fast_exp2(fmaf(s[nf][1], SC, b0s));
            s[nf][2] = fast_exp2(fmaf(s[nf][2], SC, b1s));
            s[nf][3] = fast_exp2(fmaf(s[nf][3], SC, b1s));
            rs0 += s[nf][0] + s[nf][1];
            rs1 += s[nf][2] + s[nf][3];
        }
        rs0 += __shfl_xor_sync(0xffffffffu, rs0, 1);
        rs0 += __shfl_xor_sync(0xffffffffu, rs0, 2);
        rs1 += __shfl_xor_sync(0xffffffffu, rs1, 1);
        rs1 += __shfl_xor_sync(0xffffffffu, rs1, 2);
        l0 += rs0; l1 += rs1;

        // ---- O += P V (single term; V via ldsm.trans) ----
#pragma unroll
        for (int t = 0; t < 8; t++) {
            uint32_t ph[4];
            ph[0] = pack_h2(s[2 * t][0], s[2 * t][1]);
            ph[1] = pack_h2(s[2 * t][2], s[2 * t][3]);
            ph[2] = pack_h2(s[2 * t + 1][0], s[2 * t + 1][1]);
            ph[3] = pack_h2(s[2 * t + 1][2], s[2 * t + 1][3]);
#pragma unroll
            for (int nb = 0; nb < 4; nb++) {
                uint32_t vh[4];
                uint32_t addr = st + kb_row + (uint32_t)(t * 16 * ROWB) + nb * 32;
                ldsm4t(vh[0], vh[1], vh[2], vh[3], addr);
#pragma unroll
                for (int hh = 0; hh < 2; hh++)
                    mma_f16(o[2 * nb + hh], ph, vh[2 * hh], vh[2 * hh + 1]);
            }
        }
        __syncthreads();
    }

    // ---- epilogue ----
    float inv0 = 1.0f / l0, inv1 = 1.0f / l1;
    int mr0 = q0 + wid * 16 + g;
#pragma unroll
    for (int nf = 0; nf < 8; nf++) {
        int d = h * 64 + nf * 8 + tq * 2;
        size_t i0 = ((size_t)b * 2048 + mr0) * 1024 + d;
        size_t i1 = i0 + 8 * 1024;
        *(__half2*)(Out + i0) = __float22half2_rn(
            make_float2(o[nf][0] * inv0, o[nf][1] * inv0));
        *(__half2*)(Out + i1) = __float22half2_rn(
            make_float2(o[nf][2] * inv1, o[nf][3] * inv1));
    }
}

// ---------------------------------------------------------------------------
extern "C" void kernel_launch(void* const* d_in, const int* in_sizes, int n_in,
                              void* d_out, int out_size) {
    const float* x      = (const float*)d_in[0];  // (2, 2048, 1024)
    const float* W_attn = (const float*)d_in[1];  // (1024, 3072)
    const float* b_attn = (const float*)d_in[2];  // (3072,)
    const float* W_proj = (const float*)d_in[3];  // (1024, 1024)
    const float* b_proj = (const float*)d_in[4];  // (1024,)
    float* out = (float*)d_out;                   // (2, 2048, 1024)

    __half *xs, *ks, *att, *wk, *wp;
    cudaGetSymbolAddress((void**)&xs, g_xs);
    cudaGetSymbolAddress((void**)&ks, g_ks);
    cudaGetSymbolAddress((void**)&att, g_att);
    cudaGetSymbolAddress((void**)&wk, g_wk);
    cudaGetSymbolAddress((void**)&wp, g_wp);

    cudaFuncSetAttribute(gemm_mma,
                         cudaFuncAttributeMaxDynamicSharedMemorySize, G4_SMEM);
    cudaFuncSetAttribute(attn_mma,
                         cudaFuncAttributeMaxDynamicSharedMemorySize, ATTN_SMEM_B);

    // Prep (one launch)
    prep_kernel<<<6144, 256>>>(x, xs, W_attn + 1024, W_proj, wk, wp);

    // Stage 1: K = x @ W_attn[:, D:2D] + b  -> single fp16
    gemm_mma<<<dim3(8, 16), 512, G4_SMEM>>>(xs, wk, b_attn + 1024, nullptr, ks);

    // Stage 2: FA2 attention -> att fp16
    attn_mma<<<dim3(16, 32), 256, ATTN_SMEM_B>>>(ks, att);

    // Stage 3: out = att @ W_proj + b_proj (fp32 out)
    gemm_mma<<<dim3(8, 16), 512, G4_SMEM>>>(att, wp, b_proj, out, nullptr);
}